// round 11
// baseline (speedup 1.0000x reference)
#include <cuda_runtime.h>

#define T 4096
#define H 4096
#define K 8
#define E 64
#define TK (T*K)            // 32768 slots
#define SORTB 64            // sort blocks (blocks 0..63), 512 slots each
#define NTOT (T + SORTB)    // total grid

// Scratch (no cudaMalloc allowed)
__device__ int g_rank[TK];            // stable rank within (sortblock, expert)
__device__ int g_blockcount[SORTB*E];
__device__ int g_blockbase[SORTB*E];
__device__ int g_expertbase[E];
__device__ int g_arrive;              // monotonic across replays; use &63
__device__ int g_done;                // monotonic across replays; use %NTOT
__device__ int g_flag;                // 0 at launch start; 1 = sort done; reset by last block

// ---------------------------------------------------------------------------
// One fused kernel (R4 structure; sort counting phase reduced to 3 barriers).
// Blocks [0,64): counting sort — each block owns 512 slots, processing both
// 256-slot chunks in one pass (two warp-matches, one 16-warp scan). The
// last-arriving sort block (atomic ticket) performs the cross-block +
// cross-expert scans, emits tokens_per_expert, and raises g_flag.
// Blocks [64,4160): one token each — 16KB row load, weight-sum and combined
// write all happen BEFORE the poll; only the dispatched scatter waits.
// ---------------------------------------------------------------------------
__global__ void __launch_bounds__(256) k_fused(const float4* __restrict__ x4,
                                               const float*  __restrict__ wts,
                                               const int*    __restrict__ idx,
                                               float4* __restrict__ comb4,
                                               float4* __restrict__ disp4,
                                               float*  __restrict__ tpe) {
    const int tid = threadIdx.x;

    if (blockIdx.x < SORTB) {
        // ================= SORT ROLE =================
        __shared__ int whist[16 * E];  // warps 0-7: chunk0, warps 8-15: chunk1
        __shared__ int s_last;
        const int b    = blockIdx.x;
        const int w    = tid >> 5;
        const int lane = tid & 31;

        #pragma unroll
        for (int i = 0; i < 4; i++) whist[tid + i * 256] = 0;
        __syncthreads();

        const int s0 = b * 512 + tid;
        const int s1 = s0 + 256;
        const int e0 = __ldg(&idx[s0]);
        const int e1 = __ldg(&idx[s1]);

        const unsigned m0 = __match_any_sync(0xffffffffu, e0);
        const int riw0 = __popc(m0 & ((1u << lane) - 1u));
        if ((__ffs(m0) - 1) == lane) whist[w * E + e0] = __popc(m0);
        const unsigned m1 = __match_any_sync(0xffffffffu, e1);
        const int riw1 = __popc(m1 & ((1u << lane) - 1u));
        if ((__ffs(m1) - 1) == lane) whist[(w + 8) * E + e1] = __popc(m1);
        __syncthreads();

        if (tid < E) {                 // scan 16 warp counts (chunk0 first = stable)
            int run = 0;
            #pragma unroll
            for (int ww = 0; ww < 16; ww++) {
                const int c = whist[ww * E + tid];
                whist[ww * E + tid] = run;
                run += c;
            }
            g_blockcount[b * E + tid] = run;
        }
        __syncthreads();

        g_rank[s0] = whist[w * E + e0] + riw0;
        g_rank[s1] = whist[(w + 8) * E + e1] + riw1;

        __threadfence();
        if (tid == 0) {
            const int ticket = atomicAdd(&g_arrive, 1);
            s_last = ((ticket & (SORTB - 1)) == (SORTB - 1));
        }
        __syncthreads();

        if (s_last) {
            __threadfence();
            __shared__ int tot[E];
            __shared__ int base[E];
            if (tid < E) {
                int run = 0;
                #pragma unroll
                for (int bb = 0; bb < SORTB; bb++) {
                    const int c = g_blockcount[bb * E + tid];
                    g_blockbase[bb * E + tid] = run;
                    run += c;
                }
                tot[tid] = run;
            }
            __syncthreads();
            if (tid == 0) {
                int acc = 0;
                #pragma unroll
                for (int i = 0; i < E; i++) { base[i] = acc; acc += tot[i]; }
            }
            __syncthreads();
            if (tid < E) {
                g_expertbase[tid] = base[tid];
                if (tpe) tpe[tid] = (float)tot[tid];
            }
            __threadfence();
            if (tid == 0) atomicExch(&g_flag, 1);
        }
    } else {
        // ================= TOKEN ROLE (identical to R4 best) =================
        const int t = blockIdx.x - SORTB;
        const int ROW4 = H / 4;        // 1024 float4 per row

        float4 v[4];
        #pragma unroll
        for (int i = 0; i < 4; i++)
            v[i] = __ldg(&x4[(size_t)t * ROW4 + tid + i * 256]);

        float ws = 0.f;
        #pragma unroll
        for (int k = 0; k < K; k++) ws += __ldg(&wts[t * K + k]);

        if (comb4) {
            #pragma unroll
            for (int i = 0; i < 4; i++) {
                float4 o = make_float4(v[i].x * ws, v[i].y * ws, v[i].z * ws, v[i].w * ws);
                __stcs(&comb4[(size_t)t * ROW4 + tid + i * 256], o);
            }
        }
        if (disp4) {
            // Wait for sort completion (one poller per block, backoff).
            if (tid == 0) {
                while (*((volatile int*)&g_flag) == 0) __nanosleep(64);
            }
            __syncthreads();
            __threadfence();

            int dst[K];
            #pragma unroll
            for (int k = 0; k < K; k++) {
                const int s  = t * K + k;
                const int bb = s >> 9;           // 512 slots per sort block
                const int e  = idx[s];
                dst[k] = g_expertbase[e] + g_blockbase[bb * E + e] + g_rank[s];
            }
            #pragma unroll
            for (int k = 0; k < K; k++) {
                const size_t basep = (size_t)dst[k] * ROW4;
                #pragma unroll
                for (int i = 0; i < 4; i++)
                    __stcs(&disp4[basep + tid + i * 256], v[i]);
            }
        }
    }

    // Epilogue: globally-last block resets g_flag for the next graph replay.
    __syncthreads();
    if (threadIdx.x == 0) {
        __threadfence();
        int d = atomicAdd(&g_done, 1);
        if ((d % NTOT) == (NTOT - 1)) atomicExch(&g_flag, 0);
    }
}

// ---------------------------------------------------------------------------
extern "C" void kernel_launch(void* const* d_in, const int* in_sizes, int n_in,
                              void* d_out, int out_size) {
    const float* x   = (const float*)d_in[0];
    const int*   idx = (const int*)  d_in[1];
    const float* w   = (const float*)d_in[2];
    float* out = (float*)d_out;

    const long long TH  = (long long)T * H;          // 16,777,216
    const long long TKH = (long long)TK * H;         // 134,217,728
    const long long os  = (long long)out_size;

    float* comb = nullptr;
    float* disp = nullptr;
    float* tpe  = nullptr;

    if (os >= TH + TKH) {
        comb = out;
        disp = out + TH;
        if (os >= TH + TKH + E) tpe = out + TH + TKH;
    } else if (os == TKH) {
        disp = out;                                  // dispatched-only layout
    } else {
        comb = out;                                  // combined-only layout
    }

    k_fused<<<NTOT, 256>>>((const float4*)x, w, idx,
                           (float4*)comb, (float4*)disp, tpe);
}

// round 12
// speedup vs baseline: 1.0088x; 1.0088x over previous
#include <cuda_runtime.h>

#define T 4096
#define H 4096
#define K 8
#define E 64
#define TK (T*K)            // 32768 slots
#define SORTB 64            // sort blocks (blocks 0..63), 512 slots each
#define NTOT (T + SORTB)    // total grid

// Scratch (no cudaMalloc allowed)
__device__ int g_rank[TK];            // stable rank within (sortblock, expert)
__device__ int g_blockcount[SORTB*E];
__device__ int g_blockbase[SORTB*E];
__device__ int g_expertbase[E];
__device__ unsigned g_arrive;         // monotonic sort-arrival counter (64/launch)
__device__ unsigned g_tok;            // monotonic token-entry counter (4096/launch)
__device__ unsigned g_flag;           // monotonic epoch flag: ==r+1 when launch r's sort done

// ---------------------------------------------------------------------------
// One fused kernel, epoch-flag synchronization (no resets, no exit epilogue).
// Blocks [0,64): counting sort — 512 slots each, both 256-slot chunks in one
// pass (3 barriers). Last-arriving sort block does the cross-block +
// cross-expert scans, emits tokens_per_expert, and publishes g_flag=epoch+1.
// Blocks [64,4160): one token each — 16KB row load, weight-sum and combined
// write all happen BEFORE the poll; only the dispatched scatter waits.
// ---------------------------------------------------------------------------
__global__ void __launch_bounds__(256) k_fused(const float4* __restrict__ x4,
                                               const float*  __restrict__ wts,
                                               const int*    __restrict__ idx,
                                               float4* __restrict__ comb4,
                                               float4* __restrict__ disp4,
                                               float*  __restrict__ tpe) {
    const int tid = threadIdx.x;

    if (blockIdx.x < SORTB) {
        // ================= SORT ROLE =================
        __shared__ int whist[16 * E];  // warps 0-7: chunk0, warps 8-15: chunk1
        __shared__ int s_last;
        __shared__ unsigned s_epoch;
        const int b    = blockIdx.x;
        const int w    = tid >> 5;
        const int lane = tid & 31;

        #pragma unroll
        for (int i = 0; i < 4; i++) whist[tid + i * 256] = 0;
        __syncthreads();

        const int s0 = b * 512 + tid;
        const int s1 = s0 + 256;
        const int e0 = __ldg(&idx[s0]);
        const int e1 = __ldg(&idx[s1]);

        const unsigned m0 = __match_any_sync(0xffffffffu, e0);
        const int riw0 = __popc(m0 & ((1u << lane) - 1u));
        if ((__ffs(m0) - 1) == lane) whist[w * E + e0] = __popc(m0);
        const unsigned m1 = __match_any_sync(0xffffffffu, e1);
        const int riw1 = __popc(m1 & ((1u << lane) - 1u));
        if ((__ffs(m1) - 1) == lane) whist[(w + 8) * E + e1] = __popc(m1);
        __syncthreads();

        if (tid < E) {                 // scan 16 warp counts (chunk0 first = stable)
            int run = 0;
            #pragma unroll
            for (int ww = 0; ww < 16; ww++) {
                const int c = whist[ww * E + tid];
                whist[ww * E + tid] = run;
                run += c;
            }
            g_blockcount[b * E + tid] = run;
        }
        __syncthreads();

        g_rank[s0] = whist[w * E + e0] + riw0;
        g_rank[s1] = whist[(w + 8) * E + e1] + riw1;

        __threadfence();
        if (tid == 0) {
            const unsigned ticket = atomicAdd(&g_arrive, 1u);
            s_last  = ((ticket & (SORTB - 1)) == (SORTB - 1));
            s_epoch = ticket / SORTB;           // this launch's replay index
        }
        __syncthreads();

        if (s_last) {
            __threadfence();
            __shared__ int tot[E];
            __shared__ int base[E];
            if (tid < E) {
                int run = 0;
                #pragma unroll
                for (int bb = 0; bb < SORTB; bb++) {
                    const int c = g_blockcount[bb * E + tid];
                    g_blockbase[bb * E + tid] = run;
                    run += c;
                }
                tot[tid] = run;
            }
            __syncthreads();
            if (tid == 0) {
                int acc = 0;
                #pragma unroll
                for (int i = 0; i < E; i++) { base[i] = acc; acc += tot[i]; }
            }
            __syncthreads();
            if (tid < E) {
                g_expertbase[tid] = base[tid];
                if (tpe) tpe[tid] = (float)tot[tid];
            }
            __threadfence();
            if (tid == 0) atomicMax(&g_flag, s_epoch + 1u);   // publish: no reset needed
        }
    } else {
        // ================= TOKEN ROLE (R4 best body) =================
        const int t = blockIdx.x - SORTB;
        const int ROW4 = H / 4;        // 1024 float4 per row

        // Thread 0 grabs the entry ticket while the other warps start loading.
        unsigned my_epoch = 0;
        if (tid == 0) my_epoch = atomicAdd(&g_tok, 1u) / (unsigned)T;

        float4 v[4];
        #pragma unroll
        for (int i = 0; i < 4; i++)
            v[i] = __ldg(&x4[(size_t)t * ROW4 + tid + i * 256]);

        float ws = 0.f;
        #pragma unroll
        for (int k = 0; k < K; k++) ws += __ldg(&wts[t * K + k]);

        if (comb4) {
            #pragma unroll
            for (int i = 0; i < 4; i++) {
                float4 o = make_float4(v[i].x * ws, v[i].y * ws, v[i].z * ws, v[i].w * ws);
                __stcs(&comb4[(size_t)t * ROW4 + tid + i * 256], o);
            }
        }
        if (disp4) {
            // Wait for this launch's sort epoch to be published.
            if (tid == 0) {
                while (*((volatile unsigned*)&g_flag) <= my_epoch) __nanosleep(64);
            }
            __syncthreads();
            __threadfence();

            int dst[K];
            #pragma unroll
            for (int k = 0; k < K; k++) {
                const int s  = t * K + k;
                const int bb = s >> 9;           // 512 slots per sort block
                const int e  = idx[s];
                dst[k] = g_expertbase[e] + g_blockbase[bb * E + e] + g_rank[s];
            }
            #pragma unroll
            for (int k = 0; k < K; k++) {
                const size_t basep = (size_t)dst[k] * ROW4;
                #pragma unroll
                for (int i = 0; i < 4; i++)
                    __stcs(&disp4[basep + tid + i * 256], v[i]);
            }
        }
    }
    // No epilogue: epoch flags are monotonic, nothing to reset.
}

// ---------------------------------------------------------------------------
extern "C" void kernel_launch(void* const* d_in, const int* in_sizes, int n_in,
                              void* d_out, int out_size) {
    const float* x   = (const float*)d_in[0];
    const int*   idx = (const int*)  d_in[1];
    const float* w   = (const float*)d_in[2];
    float* out = (float*)d_out;

    const long long TH  = (long long)T * H;          // 16,777,216
    const long long TKH = (long long)TK * H;         // 134,217,728
    const long long os  = (long long)out_size;

    float* comb = nullptr;
    float* disp = nullptr;
    float* tpe  = nullptr;

    if (os >= TH + TKH) {
        comb = out;
        disp = out + TH;
        if (os >= TH + TKH + E) tpe = out + TH + TKH;
    } else if (os == TKH) {
        disp = out;                                  // dispatched-only layout
    } else {
        comb = out;                                  // combined-only layout
    }

    k_fused<<<NTOT, 256>>>((const float4*)x, w, idx,
                           (float4*)comb, (float4*)disp, tpe);
}

// round 13
// speedup vs baseline: 1.0355x; 1.0264x over previous
#include <cuda_runtime.h>

#define T 4096
#define H 4096
#define K 8
#define E 64
#define TK (T*K)            // 32768 slots
#define SORTB 64            // sort blocks (blocks 0..63), 512 slots each
#define NTOT (T + SORTB)    // total grid
#define NFLAG 32            // flag replicas, one per 128B line

// Scratch (no cudaMalloc allowed)
__device__ int g_rank[TK];            // stable rank within (sortblock, expert)
__device__ int g_blockcount[SORTB*E];
__device__ int g_blockbase[SORTB*E];
__device__ int g_expertbase[E];
__device__ unsigned g_arrive;         // monotonic sort-arrival counter (64/launch)
__device__ unsigned g_tok;            // monotonic token-entry counter (4096/launch)
__device__ unsigned g_flags[NFLAG * 32];  // epoch flags, replica i at [i*32] (128B apart)

// ---------------------------------------------------------------------------
// One fused kernel, epoch-flag sync with 32 replicated flags (no resets).
// Blocks [0,64): counting sort — 512 slots each, both 256-slot chunks in one
// pass. Last-arriving sort block does cross-block + cross-expert scans, emits
// tokens_per_expert, then publishes epoch+1 to all 32 flag replicas.
// Blocks [64,4160): one token each — 16KB row load, weight-sum, idx staging
// to smem, and the combined write all happen BEFORE the poll; the poll hits a
// block-specific flag replica; the post-flag chain is 3 parallel L2 loads.
// ---------------------------------------------------------------------------
__global__ void __launch_bounds__(256) k_fused(const float4* __restrict__ x4,
                                               const float*  __restrict__ wts,
                                               const int*    __restrict__ idx,
                                               float4* __restrict__ comb4,
                                               float4* __restrict__ disp4,
                                               float*  __restrict__ tpe) {
    const int tid = threadIdx.x;

    if (blockIdx.x < SORTB) {
        // ================= SORT ROLE =================
        __shared__ int whist[16 * E];  // warps 0-7: chunk0, warps 8-15: chunk1
        __shared__ int s_last;
        __shared__ unsigned s_epoch;
        const int b    = blockIdx.x;
        const int w    = tid >> 5;
        const int lane = tid & 31;

        #pragma unroll
        for (int i = 0; i < 4; i++) whist[tid + i * 256] = 0;
        __syncthreads();

        const int s0 = b * 512 + tid;
        const int s1 = s0 + 256;
        const int e0 = __ldg(&idx[s0]);
        const int e1 = __ldg(&idx[s1]);

        const unsigned m0 = __match_any_sync(0xffffffffu, e0);
        const int riw0 = __popc(m0 & ((1u << lane) - 1u));
        if ((__ffs(m0) - 1) == lane) whist[w * E + e0] = __popc(m0);
        const unsigned m1 = __match_any_sync(0xffffffffu, e1);
        const int riw1 = __popc(m1 & ((1u << lane) - 1u));
        if ((__ffs(m1) - 1) == lane) whist[(w + 8) * E + e1] = __popc(m1);
        __syncthreads();

        if (tid < E) {                 // scan 16 warp counts (chunk0 first = stable)
            int run = 0;
            #pragma unroll
            for (int ww = 0; ww < 16; ww++) {
                const int c = whist[ww * E + tid];
                whist[ww * E + tid] = run;
                run += c;
            }
            g_blockcount[b * E + tid] = run;
        }
        __syncthreads();

        g_rank[s0] = whist[w * E + e0] + riw0;
        g_rank[s1] = whist[(w + 8) * E + e1] + riw1;

        __threadfence();
        if (tid == 0) {
            const unsigned ticket = atomicAdd(&g_arrive, 1u);
            s_last  = ((ticket & (SORTB - 1)) == (SORTB - 1));
            s_epoch = ticket / SORTB;           // this launch's replay index
        }
        __syncthreads();

        if (s_last) {
            __threadfence();
            __shared__ int tot[E];
            __shared__ int base[E];
            if (tid < E) {
                int run = 0;
                #pragma unroll
                for (int bb = 0; bb < SORTB; bb++) {
                    const int c = g_blockcount[bb * E + tid];
                    g_blockbase[bb * E + tid] = run;
                    run += c;
                }
                tot[tid] = run;
            }
            __syncthreads();
            if (tid == 0) {
                int acc = 0;
                #pragma unroll
                for (int i = 0; i < E; i++) { base[i] = acc; acc += tot[i]; }
            }
            __syncthreads();
            if (tid < E) {
                g_expertbase[tid] = base[tid];
                if (tpe) tpe[tid] = (float)tot[tid];
            }
            __threadfence();
            if (tid < NFLAG) atomicMax(&g_flags[tid * 32], s_epoch + 1u);
        }
    } else {
        // ================= TOKEN ROLE =================
        const int t = blockIdx.x - SORTB;
        const int ROW4 = H / 4;        // 1024 float4 per row
        __shared__ int sidx[K];

        // Thread 0 grabs the entry ticket while the other warps start loading.
        unsigned my_epoch = 0;
        if (tid == 0) my_epoch = atomicAdd(&g_tok, 1u) / (unsigned)T;
        if (tid < K) sidx[tid] = __ldg(&idx[t * K + tid]);   // pre-poll staging

        float4 v[4];
        #pragma unroll
        for (int i = 0; i < 4; i++)
            v[i] = __ldg(&x4[(size_t)t * ROW4 + tid + i * 256]);

        float ws = 0.f;
        #pragma unroll
        for (int k = 0; k < K; k++) ws += __ldg(&wts[t * K + k]);

        if (comb4) {
            #pragma unroll
            for (int i = 0; i < 4; i++) {
                float4 o = make_float4(v[i].x * ws, v[i].y * ws, v[i].z * ws, v[i].w * ws);
                __stcs(&comb4[(size_t)t * ROW4 + tid + i * 256], o);
            }
        }
        if (disp4) {
            // Wait on this block's flag replica.
            const int fi = (blockIdx.x & (NFLAG - 1)) * 32;
            if (tid == 0) {
                while (*((volatile unsigned*)&g_flags[fi]) <= my_epoch) __nanosleep(64);
            }
            __syncthreads();
            __threadfence();

            int dst[K];
            #pragma unroll
            for (int k = 0; k < K; k++) {
                const int s  = t * K + k;
                const int bb = s >> 9;           // 512 slots per sort block
                const int e  = sidx[k];          // already staged: 3 parallel loads
                dst[k] = g_expertbase[e] + g_blockbase[bb * E + e] + g_rank[s];
            }
            #pragma unroll
            for (int k = 0; k < K; k++) {
                const size_t basep = (size_t)dst[k] * ROW4;
                #pragma unroll
                for (int i = 0; i < 4; i++)
                    __stcs(&disp4[basep + tid + i * 256], v[i]);
            }
        }
    }
    // No epilogue: epoch flags are monotonic, nothing to reset.
}

// ---------------------------------------------------------------------------
extern "C" void kernel_launch(void* const* d_in, const int* in_sizes, int n_in,
                              void* d_out, int out_size) {
    const float* x   = (const float*)d_in[0];
    const int*   idx = (const int*)  d_in[1];
    const float* w   = (const float*)d_in[2];
    float* out = (float*)d_out;

    const long long TH  = (long long)T * H;          // 16,777,216
    const long long TKH = (long long)TK * H;         // 134,217,728
    const long long os  = (long long)out_size;

    float* comb = nullptr;
    float* disp = nullptr;
    float* tpe  = nullptr;

    if (os >= TH + TKH) {
        comb = out;
        disp = out + TH;
        if (os >= TH + TKH + E) tpe = out + TH + TKH;
    } else if (os == TKH) {
        disp = out;                                  // dispatched-only layout
    } else {
        comb = out;                                  // combined-only layout
    }

    k_fused<<<NTOT, 256>>>((const float4*)x, w, idx,
                           (float4*)comb, (float4*)disp, tpe);
}